// round 2
// baseline (speedup 1.0000x reference)
#include <cuda_runtime.h>
#include <math.h>

// Problem constants
#define N_    256
#define C_    512
#define T_    4
#define HW_   64
#define L_    256          // T_*HW_
#define SLAB  131072       // N_*C_  (stride of one [n][c] slab in [loc][n][c] layout)

// ---------------- scratch (device globals; no allocation allowed) ----------------
__device__ float g_q[33554432];      // [loc][n][c]
__device__ float g_k[33554432];
__device__ float g_v[33554432];
__device__ float g_virt[33554432];   // [loc][n][c]
__device__ float g_att[16777216];    // [loc][i][j]
__device__ float g_wqkv[9 * 512 * 1536];  // [tap][ic][oc'] oc' = conv*512+oc
__device__ float g_wc[9 * 512 * 512];     // [tap][ic][oc]
__device__ float2 g_stats[256];           // per-n (mu, rstd)

// ---------------- weight transforms: W[o][i][tap] -> Wt[tap][i][o] ----------------
__global__ void wt_qkv_kernel(const float* __restrict__ wq,
                              const float* __restrict__ wk,
                              const float* __restrict__ wv) {
    int total = 9 * 512 * 1536;
    for (int i = blockIdx.x * blockDim.x + threadIdx.x; i < total;
         i += gridDim.x * blockDim.x) {
        int oc2 = i % 1536;
        int ic  = (i / 1536) % 512;
        int tap = i / (1536 * 512);
        const float* src = (oc2 < 512) ? wq : (oc2 < 1024) ? wk : wv;
        int oc = oc2 & 511;
        g_wqkv[i] = src[((size_t)oc * 512 + ic) * 9 + tap];
    }
}

__global__ void wt_c_kernel(const float* __restrict__ wc) {
    int total = 9 * 512 * 512;
    for (int i = blockIdx.x * blockDim.x + threadIdx.x; i < total;
         i += gridDim.x * blockDim.x) {
        int oc  = i & 511;
        int ic  = (i >> 9) & 511;
        int tap = i >> 18;
        g_wc[i] = wc[((size_t)oc * 512 + ic) * 9 + tap];
    }
}

// ---------------- conv kernels -----------------------------------------------------
// Block: 256 threads, computes a 64(oc) x 64(pixel) tile for one (n,t).
// smem X tile is [64 ic][10x10] haloed so a tap shift is a constant offset add.

#define CONV_BODY(LOAD_EXPR, WPTR, OCW)                                              \
    __shared__ __align__(16) float sX[64 * 100];                                     \
    __shared__ __align__(16) float sW[64 * 64];                                      \
    const int tid = threadIdx.x;                                                     \
    const int tx = tid & 15, ty = tid >> 4;                                          \
    const int nt = blockIdx.y;                                                       \
    const int n = nt >> 2, t = nt & 3;                                               \
    const int oc0 = blockIdx.x * 64;                                                 \
    int baseo[4];                                                                    \
    _Pragma("unroll") for (int j = 0; j < 4; j++) {                                  \
        int p = tx + 16 * j;                                                         \
        baseo[j] = (p >> 3) * 10 + (p & 7);                                          \
    }                                                                                \
    float acc[4][4];                                                                 \
    _Pragma("unroll") for (int i = 0; i < 4; i++)                                    \
        _Pragma("unroll") for (int j = 0; j < 4; j++) acc[i][j] = 0.f;               \
    for (int cc = 0; cc < C_; cc += 64) {                                            \
        for (int idx = tid; idx < 6400; idx += 256) {                                \
            int icl = idx / 100;                                                     \
            int pp = idx - icl * 100;                                                \
            int ph = pp / 10, pw = pp - ph * 10;                                     \
            int h = ph - 1, w = pw - 1;                                              \
            float val = 0.f;                                                         \
            if ((unsigned)h < 8u && (unsigned)w < 8u) {                              \
                int ic = cc + icl;                                                   \
                val = (LOAD_EXPR);                                                   \
            }                                                                        \
            sX[idx] = val;                                                           \
        }                                                                            \
        __syncthreads();                                                             \
        for (int tap = 0; tap < 9; tap++) {                                          \
            const float* wsrc = (WPTR) + ((size_t)tap * C_ + cc) * (OCW) + oc0;      \
            for (int idx = tid; idx < 4096; idx += 256) {                            \
                int icl = idx >> 6, ocl = idx & 63;                                  \
                sW[idx] = wsrc[(size_t)icl * (OCW) + ocl];                           \
            }                                                                        \
            __syncthreads();                                                         \
            const int off = (tap / 3) * 10 + (tap % 3);                              \
            _Pragma("unroll 4") for (int icl = 0; icl < 64; icl++) {                 \
                const float4 a = *(const float4*)&sW[(icl << 6) + (ty << 2)];        \
                const float* xrow = &sX[icl * 100 + off];                            \
                float b0 = xrow[baseo[0]];                                           \
                float b1 = xrow[baseo[1]];                                           \
                float b2 = xrow[baseo[2]];                                           \
                float b3 = xrow[baseo[3]];                                           \
                acc[0][0] += a.x * b0; acc[0][1] += a.x * b1;                        \
                acc[0][2] += a.x * b2; acc[0][3] += a.x * b3;                        \
                acc[1][0] += a.y * b0; acc[1][1] += a.y * b1;                        \
                acc[1][2] += a.y * b2; acc[1][3] += a.y * b3;                        \
                acc[2][0] += a.z * b0; acc[2][1] += a.z * b1;                        \
                acc[2][2] += a.z * b2; acc[2][3] += a.z * b3;                        \
                acc[3][0] += a.w * b0; acc[3][1] += a.w * b1;                        \
                acc[3][2] += a.w * b2; acc[3][3] += a.w * b3;                        \
            }                                                                        \
            __syncthreads();                                                         \
        }                                                                            \
    }

// Pass 1: fused q,k,v conv.  Input x [n][c][t][hw].  Output [loc][n][c].
__global__ __launch_bounds__(256) void conv_qkv_kernel(const float* __restrict__ x) {
    CONV_BODY(x[(((size_t)n * C_ + ic) * T_ + t) * HW_ + h * 8 + w], g_wqkv, 1536)
    float* dst;
    int ocb;
    if (oc0 < 512)       { dst = g_q; ocb = oc0; }
    else if (oc0 < 1024) { dst = g_k; ocb = oc0 - 512; }
    else                 { dst = g_v; ocb = oc0 - 1024; }
#pragma unroll
    for (int j = 0; j < 4; j++) {
        int p = tx + 16 * j;
        size_t base = ((size_t)(t * HW_ + p)) * SLAB + (size_t)n * C_ + ocb + (ty << 2);
        *(float4*)&dst[base] = make_float4(acc[0][j], acc[1][j], acc[2][j], acc[3][j]);
    }
}

// Pass 2: conv(virt_norm, Wc) + x -> out.  Input g_virt [loc][n][c].
__global__ __launch_bounds__(256) void conv_out_kernel(const float* __restrict__ x,
                                                       float* __restrict__ out) {
    CONV_BODY(g_virt[((size_t)(t * HW_ + h * 8 + w)) * SLAB + (size_t)n * C_ + ic], g_wc, 512)
#pragma unroll
    for (int j = 0; j < 4; j++) {
        int p = tx + 16 * j;
#pragma unroll
        for (int i = 0; i < 4; i++) {
            int oc = oc0 + (ty << 2) + i;
            size_t g = (((size_t)n * C_ + oc) * T_ + t) * HW_ + p;
            out[g] = x[g] + acc[i][j];
        }
    }
}

// ---------------- attention: S = scale * q k^T with group mask ---------------------
__global__ __launch_bounds__(256) void attn_scores_kernel(const int* __restrict__ roi) {
    __shared__ __align__(16) float sQ[32 * 68];
    __shared__ __align__(16) float sK[32 * 68];
    const int tid = threadIdx.x;
    const int tx = tid & 15, ty = tid >> 4;
    const int loc = blockIdx.y;
    const int it = blockIdx.x >> 2, jt = blockIdx.x & 3;
    const int i0 = it * 64, j0 = jt * 64;
    const size_t qb = (size_t)loc * SLAB + (size_t)i0 * C_;
    const size_t kb = (size_t)loc * SLAB + (size_t)j0 * C_;
    float acc[4][4];
#pragma unroll
    for (int i = 0; i < 4; i++)
#pragma unroll
        for (int j = 0; j < 4; j++) acc[i][j] = 0.f;

    for (int cc = 0; cc < C_; cc += 32) {
#pragma unroll
        for (int u = 0; u < 2; u++) {
            int idx = u * 256 + tid;
            int r = idx >> 3, co = idx & 7;
            float4 vq = *(const float4*)&g_q[qb + (size_t)r * C_ + cc + co * 4];
            float4 vk = *(const float4*)&g_k[kb + (size_t)r * C_ + cc + co * 4];
            sQ[(co * 4 + 0) * 68 + r] = vq.x; sQ[(co * 4 + 1) * 68 + r] = vq.y;
            sQ[(co * 4 + 2) * 68 + r] = vq.z; sQ[(co * 4 + 3) * 68 + r] = vq.w;
            sK[(co * 4 + 0) * 68 + r] = vk.x; sK[(co * 4 + 1) * 68 + r] = vk.y;
            sK[(co * 4 + 2) * 68 + r] = vk.z; sK[(co * 4 + 3) * 68 + r] = vk.w;
        }
        __syncthreads();
#pragma unroll 8
        for (int kk = 0; kk < 32; kk++) {
            float4 a = *(const float4*)&sQ[kk * 68 + (ty << 2)];
            float4 b = *(const float4*)&sK[kk * 68 + (tx << 2)];
            acc[0][0] += a.x * b.x; acc[0][1] += a.x * b.y; acc[0][2] += a.x * b.z; acc[0][3] += a.x * b.w;
            acc[1][0] += a.y * b.x; acc[1][1] += a.y * b.y; acc[1][2] += a.y * b.z; acc[1][3] += a.y * b.w;
            acc[2][0] += a.z * b.x; acc[2][1] += a.z * b.y; acc[2][2] += a.z * b.z; acc[2][3] += a.z * b.w;
            acc[3][0] += a.w * b.x; acc[3][1] += a.w * b.y; acc[3][2] += a.w * b.z; acc[3][3] += a.w * b.w;
        }
        __syncthreads();
    }
    const float scale = 0.044194173824159216f;  // 1/sqrt(512)
    int ri[4], rj[4];
#pragma unroll
    for (int i = 0; i < 4; i++) ri[i] = roi[i0 + (ty << 2) + i];
#pragma unroll
    for (int j = 0; j < 4; j++) rj[j] = roi[j0 + (tx << 2) + j];
#pragma unroll
    for (int i = 0; i < 4; i++) {
        float4 o;
        o.x = (ri[i] == rj[0]) ? acc[i][0] * scale : -1e30f;
        o.y = (ri[i] == rj[1]) ? acc[i][1] * scale : -1e30f;
        o.z = (ri[i] == rj[2]) ? acc[i][2] * scale : -1e30f;
        o.w = (ri[i] == rj[3]) ? acc[i][3] * scale : -1e30f;
        size_t base = (size_t)loc * 65536 + (size_t)(i0 + (ty << 2) + i) * 256 + j0 + (tx << 2);
        *(float4*)&g_att[base] = o;
    }
}

// ---------------- softmax over j (row length 256), one warp per row ----------------
__global__ __launch_bounds__(256) void softmax_kernel() {
    int row = blockIdx.x * 8 + (threadIdx.x >> 5);
    int lane = threadIdx.x & 31;
    float4* base = (float4*)(g_att + (size_t)row * 256);
    float4 v0 = base[lane];
    float4 v1 = base[lane + 32];
    float m = fmaxf(fmaxf(fmaxf(v0.x, v0.y), fmaxf(v0.z, v0.w)),
                    fmaxf(fmaxf(v1.x, v1.y), fmaxf(v1.z, v1.w)));
#pragma unroll
    for (int o = 16; o; o >>= 1) m = fmaxf(m, __shfl_xor_sync(0xffffffffu, m, o));
    v0.x = expf(v0.x - m); v0.y = expf(v0.y - m); v0.z = expf(v0.z - m); v0.w = expf(v0.w - m);
    v1.x = expf(v1.x - m); v1.y = expf(v1.y - m); v1.z = expf(v1.z - m); v1.w = expf(v1.w - m);
    float s = v0.x + v0.y + v0.z + v0.w + v1.x + v1.y + v1.z + v1.w;
#pragma unroll
    for (int o = 16; o; o >>= 1) s += __shfl_xor_sync(0xffffffffu, s, o);
    float inv = 1.f / s;
    v0.x *= inv; v0.y *= inv; v0.z *= inv; v0.w *= inv;
    v1.x *= inv; v1.y *= inv; v1.z *= inv; v1.w *= inv;
    base[lane] = v0;
    base[lane + 32] = v1;
}

// ---------------- virt = att @ v ---------------------------------------------------
__global__ __launch_bounds__(256) void attn_v_kernel() {
    __shared__ __align__(16) float sA[32 * 68];  // [j][i]
    __shared__ __align__(16) float sV[32 * 68];  // [j][c]
    const int tid = threadIdx.x;
    const int tx = tid & 15, ty = tid >> 4;
    const int loc = blockIdx.y;
    const int it = blockIdx.x >> 3, ct = blockIdx.x & 7;
    const int i0 = it * 64, c0 = ct * 64;
    float acc[4][4];
#pragma unroll
    for (int i = 0; i < 4; i++)
#pragma unroll
        for (int j = 0; j < 4; j++) acc[i][j] = 0.f;

    for (int cc = 0; cc < 256; cc += 32) {
#pragma unroll
        for (int u = 0; u < 2; u++) {
            int idx = u * 256 + tid;
            // A chunk: 64 i-rows x 32 j-cols, store transposed
            {
                int r = idx >> 3, co = idx & 7;
                float4 va = *(const float4*)&g_att[(size_t)loc * 65536 +
                                                   (size_t)(i0 + r) * 256 + cc + co * 4];
                sA[(co * 4 + 0) * 68 + r] = va.x; sA[(co * 4 + 1) * 68 + r] = va.y;
                sA[(co * 4 + 2) * 68 + r] = va.z; sA[(co * 4 + 3) * 68 + r] = va.w;
            }
            // V chunk: 32 j-rows x 64 c-cols, natural layout
            {
                int jr = idx >> 4, co = idx & 15;
                float4 vv = *(const float4*)&g_v[(size_t)loc * SLAB +
                                                 (size_t)(cc + jr) * C_ + c0 + co * 4];
                *(float4*)&sV[jr * 68 + co * 4] = vv;
            }
        }
        __syncthreads();
#pragma unroll 8
        for (int kk = 0; kk < 32; kk++) {
            float4 a = *(const float4*)&sA[kk * 68 + (ty << 2)];
            float4 b = *(const float4*)&sV[kk * 68 + (tx << 2)];
            acc[0][0] += a.x * b.x; acc[0][1] += a.x * b.y; acc[0][2] += a.x * b.z; acc[0][3] += a.x * b.w;
            acc[1][0] += a.y * b.x; acc[1][1] += a.y * b.y; acc[1][2] += a.y * b.z; acc[1][3] += a.y * b.w;
            acc[2][0] += a.z * b.x; acc[2][1] += a.z * b.y; acc[2][2] += a.z * b.z; acc[2][3] += a.z * b.w;
            acc[3][0] += a.w * b.x; acc[3][1] += a.w * b.y; acc[3][2] += a.w * b.z; acc[3][3] += a.w * b.w;
        }
        __syncthreads();
    }
#pragma unroll
    for (int i = 0; i < 4; i++) {
        size_t base = (size_t)loc * SLAB + (size_t)(i0 + (ty << 2) + i) * C_ + c0 + (tx << 2);
        *(float4*)&g_virt[base] = make_float4(acc[i][0], acc[i][1], acc[i][2], acc[i][3]);
    }
}

// ---------------- GroupNorm(1 group) stats + normalize + relu ----------------------
__global__ __launch_bounds__(256) void gn_stats_kernel() {
    const int n = blockIdx.x, tid = threadIdx.x;
    float s = 0.f, sq = 0.f;
    for (int loc = 0; loc < L_; loc++) {
        size_t base = (size_t)loc * SLAB + (size_t)n * C_;
        float a = g_virt[base + tid];
        float b = g_virt[base + tid + 256];
        s += a + b;
        sq += a * a + b * b;
    }
    __shared__ float rs[256], rq[256];
    rs[tid] = s; rq[tid] = sq;
    __syncthreads();
    for (int o = 128; o > 0; o >>= 1) {
        if (tid < o) { rs[tid] += rs[tid + o]; rq[tid] += rq[tid + o]; }
        __syncthreads();
    }
    if (tid == 0) {
        const float inv = 1.f / 131072.f;
        float mu = rs[0] * inv;
        float var = rq[0] * inv - mu * mu;
        g_stats[n] = make_float2(mu, rsqrtf(var + 1e-5f));
    }
}

__global__ __launch_bounds__(256) void gn_norm_kernel(const float* __restrict__ gamma,
                                                      const float* __restrict__ beta) {
    size_t i = (size_t)blockIdx.x * 256 + threadIdx.x;   // grid sized exactly
    int c = (int)(i & 511);
    int n = (int)((i >> 9) & 255);
    float2 st = g_stats[n];
    float val = (g_virt[i] - st.x) * st.y * gamma[c] + beta[c];
    g_virt[i] = fmaxf(val, 0.f);
}

// ---------------- launch -----------------------------------------------------------
extern "C" void kernel_launch(void* const* d_in, const int* in_sizes, int n_in,
                              void* d_out, int out_size) {
    const float* x     = (const float*)d_in[0];
    const int*   roi   = (const int*)d_in[1];
    const float* Wq    = (const float*)d_in[2];
    const float* Wk    = (const float*)d_in[3];
    const float* Wv    = (const float*)d_in[4];
    const float* Wc    = (const float*)d_in[5];
    const float* gamma = (const float*)d_in[6];
    const float* beta  = (const float*)d_in[7];
    float* out = (float*)d_out;

    wt_qkv_kernel<<<4096, 256>>>(Wq, Wk, Wv);
    wt_c_kernel<<<2048, 256>>>(Wc);

    conv_qkv_kernel<<<dim3(24, 1024), 256>>>(x);          // q,k,v

    attn_scores_kernel<<<dim3(16, 256), 256>>>(roi);      // S + mask
    softmax_kernel<<<8192, 256>>>();                      // row softmax
    attn_v_kernel<<<dim3(32, 256), 256>>>();              // virt = att @ v

    gn_stats_kernel<<<256, 256>>>();
    gn_norm_kernel<<<131072, 256>>>(gamma, beta);

    conv_out_kernel<<<dim3(8, 1024), 256>>>(x, out);      // x + conv(virt, Wc)
}

// round 4
// speedup vs baseline: 4.2292x; 4.2292x over previous
#include <cuda_runtime.h>
#include <cuda_fp16.h>
#include <math.h>
#include <stdint.h>

// ---------------- problem constants ----------------
#define N_    256
#define C_    512
#define SLAB  131072            // N_*C_

// ---------------- device scratch (no allocation allowed) ----------------
__device__ __align__(256) float g_q[33554432];      // [loc][n][c] fp32
__device__ __align__(256) float g_k[33554432];
__device__ __align__(256) float g_v[33554432];
__device__ __align__(256) float g_virt[33554432];   // [loc][n][c] fp32 (pre-GN)
__device__ __align__(256) float g_att[16777216];    // [loc][i][j]
__device__ float2 g_stats[256];

// fp16 packed operands for HMMA convs
__device__ __align__(256) __half g_xh[33554432];    // x hi  [t][n][pix][ic]
__device__ __align__(256) __half g_xl[33554432];    // x lo
__device__ __align__(256) __half g_vh[33554432];    // virt post-GN hi [loc][n][c]
__device__ __align__(256) __half g_vl[33554432];    // virt lo
__device__ __align__(256) __half g_wq[7077888];     // qkv weights [tap][ocp(1536)][ic]
__device__ __align__(256) __half g_wc[2359296];     // Wc [tap][oc][ic]

// ---------------- asm helpers ----------------
__device__ __forceinline__ uint32_t smem_u32_of(const void* p) {
    uint32_t a;
    asm("{ .reg .u64 t; cvta.to.shared.u64 t, %1; cvt.u32.u64 %0, t; }" : "=r"(a) : "l"(p));
    return a;
}
#define CPA(dst, src, sz) \
    asm volatile("cp.async.cg.shared.global [%0], [%1], 16, %2;" \
        :: "r"(dst), "l"(src), "r"(sz) : "memory")
#define CPA_COMMIT() asm volatile("cp.async.commit_group;" ::: "memory")

__device__ __forceinline__ void ldsm4(uint32_t r[4], uint32_t addr) {
    asm volatile("ldmatrix.sync.aligned.m8n8.x4.shared.b16 {%0,%1,%2,%3}, [%4];"
        : "=r"(r[0]), "=r"(r[1]), "=r"(r[2]), "=r"(r[3]) : "r"(addr));
}
__device__ __forceinline__ void mma16816(float c[4], const uint32_t a[4],
                                         uint32_t b0, uint32_t b1) {
    asm volatile(
        "mma.sync.aligned.m16n8k16.row.col.f32.f16.f16.f32 "
        "{%0,%1,%2,%3}, {%4,%5,%6,%7}, {%8,%9}, {%0,%1,%2,%3};"
        : "+f"(c[0]), "+f"(c[1]), "+f"(c[2]), "+f"(c[3])
        : "r"(a[0]), "r"(a[1]), "r"(a[2]), "r"(a[3]), "r"(b0), "r"(b1));
}

// ---------------- prepack kernels ----------------
// x [n][c][t][hw] fp32 -> g_xh/g_xl [t][n][pix][ic] fp16 hi/lo
__global__ __launch_bounds__(256) void pack_x_kernel(const float* __restrict__ x) {
    __shared__ float sT[64 * 65];
    int icb = blockIdx.x;            // 0..7
    int nt  = blockIdx.y;            // 0..1023
    int n = nt >> 2, t = nt & 3;
    int ic0 = icb * 64;
    int tid = threadIdx.x;
#pragma unroll 4
    for (int rep = 0; rep < 16; rep++) {
        int e = rep * 256 + tid;
        int i = e >> 6, p = e & 63;
        sT[i * 65 + p] = x[(((size_t)n * C_ + ic0 + i) * 4 + t) * 64 + p];
    }
    __syncthreads();
#pragma unroll 4
    for (int rep = 0; rep < 16; rep++) {
        int e = rep * 256 + tid;
        int p = e >> 6, i = e & 63;
        float v = sT[i * 65 + p];
        __half h = __float2half_rn(v);
        __half l = __float2half_rn(v - __half2float(h));
        size_t o = (size_t)t * 8388608 + (size_t)n * 32768 + (size_t)p * 512 + ic0 + i;
        g_xh[o] = h;
        g_xl[o] = l;
    }
}

__global__ __launch_bounds__(256) void pack_wqkv_kernel(const float* __restrict__ wq,
                                                        const float* __restrict__ wk,
                                                        const float* __restrict__ wv) {
    int idx = blockIdx.x * 256 + threadIdx.x;    // 9*1536*512 = 7077888
    if (idx >= 7077888) return;
    int ic  = idx & 511;
    int ocp = (idx >> 9) % 1536;
    int tap = idx / (1536 * 512);
    const float* src = (ocp < 512) ? wq : (ocp < 1024) ? wk : wv;
    int oc = ocp & 511;
    g_wq[idx] = __float2half_rn(src[((size_t)oc * 512 + ic) * 9 + tap]);
}

__global__ __launch_bounds__(256) void pack_wc_kernel(const float* __restrict__ wc) {
    int idx = blockIdx.x * 256 + threadIdx.x;    // 9*512*512 = 2359296
    if (idx >= 2359296) return;
    int ic  = idx & 511;
    int oc  = (idx >> 9) & 511;
    int tap = idx >> 18;
    g_wc[idx] = __float2half_rn(wc[((size_t)oc * 512 + ic) * 9 + tap]);
}

// ---------------- HMMA conv mainloop ----------------
// CTA computes D[128 oc x 128 (2n x 64pix)] for one t, accumulating over
// 72 stages (9 taps x 8 ic-blocks of 64) with B in hi+lo fp16 (2-pass split).
// smem per buffer: A 16KB | Bhi 16KB | Blo 16KB, double buffered (96KB).

struct ConvArgs {
    const __half* w; int ocw; int oc0;
    const __half* dh; const __half* dl;
    size_t base; int sq; int sn; int n0;
};

__device__ __forceinline__ void conv_accum(float acc[4][4][4], const ConvArgs& A_) {
    extern __shared__ char smem[];
    const uint32_t smem_b = smem_u32_of(smem);
    const int tid = threadIdx.x;
    const int lane = tid & 31, wid = tid >> 5;
    const int wm = wid >> 2, wn = wid & 3;

    auto load_stage = [&](int s) {
        const int buf = s & 1;
        const int tap = s >> 3, icb = s & 7;
        const int dhh = tap / 3 - 1, dww = tap % 3 - 1;
        const uint32_t ab = smem_b + buf * 49152;
#pragma unroll
        for (int kk = 0; kk < 12; kk++) {
            int task = tid + kk * 256;
            int reg = task >> 10;            // 0=A, 1=Bhi, 2=Blo
            int q = task & 1023;
            int r = q >> 3, c = q & 7;
            uint32_t dst = ab + reg * 16384 + r * 128 + 16 * (c ^ (r & 7));
            if (reg == 0) {
                const __half* src = A_.w +
                    ((size_t)(tap * A_.ocw + A_.oc0 + r)) * 512 + icb * 64 + c * 8;
                CPA(dst, src, 16);
            } else {
                int n = A_.n0 + (r >> 6), p = r & 63;
                int hh = (p >> 3) + dhh, ww = (p & 7) + dww;
                bool ok = ((unsigned)hh < 8u) && ((unsigned)ww < 8u);
                const __half* bsrc = (reg == 1) ? A_.dh : A_.dl;
                const __half* src = bsrc + A_.base +
                    (size_t)(ok ? (hh * 8 + ww) : 0) * A_.sq +
                    (size_t)n * A_.sn + icb * 64 + c * 8;
                CPA(dst, src, ok ? 16 : 0);
            }
        }
        CPA_COMMIT();
    };

    auto compute_stage = [&](int buf) {
        const uint32_t ab = smem_b + buf * 49152;
#pragma unroll
        for (int prec = 0; prec < 2; prec++) {
            const uint32_t bb = ab + 16384 + prec * 16384;
#pragma unroll
            for (int ks = 0; ks < 4; ks++) {
                uint32_t Af[4][4];
#pragma unroll
                for (int mf = 0; mf < 4; mf++) {
                    int r = wm * 64 + mf * 16 + (lane & 7) + ((lane >> 3) & 1) * 8;
                    int kc = ks * 2 + (lane >> 4);
                    ldsm4(Af[mf], ab + r * 128 + 16 * (kc ^ (r & 7)));
                }
#pragma unroll
                for (int nb2 = 0; nb2 < 2; nb2++) {
                    uint32_t Bf[4];
                    int r = wn * 32 + nb2 * 16 + (lane & 7) + ((lane >> 4) << 3);
                    int kc = ks * 2 + ((lane >> 3) & 1);
                    ldsm4(Bf, bb + r * 128 + 16 * (kc ^ (r & 7)));
#pragma unroll
                    for (int mf = 0; mf < 4; mf++) {
                        mma16816(acc[mf][nb2 * 2 + 0], Af[mf], Bf[0], Bf[1]);
                        mma16816(acc[mf][nb2 * 2 + 1], Af[mf], Bf[2], Bf[3]);
                    }
                }
            }
        }
    };

    load_stage(0);
    for (int s = 0; s < 72; s++) {
        if (s + 1 < 72) {
            load_stage(s + 1);
            asm volatile("cp.async.wait_group 1;" ::: "memory");
        } else {
            asm volatile("cp.async.wait_group 0;" ::: "memory");
        }
        __syncthreads();
        compute_stage(s & 1);
        __syncthreads();
    }
}

// ---------------- conv qkv ----------------
__global__ __launch_bounds__(256, 2) void hconv_qkv_kernel() {
    float acc[4][4][4];
#pragma unroll
    for (int a = 0; a < 4; a++)
#pragma unroll
        for (int b = 0; b < 4; b++)
#pragma unroll
            for (int c = 0; c < 4; c++) acc[a][b][c] = 0.f;

    const int mt = blockIdx.x;            // 0..11
    const int y  = blockIdx.y;            // 0..511
    const int t = y >> 7, n0 = (y & 127) * 2;

    ConvArgs ar;
    ar.w = g_wq; ar.ocw = 1536; ar.oc0 = mt * 128;
    ar.dh = g_xh; ar.dl = g_xl;
    ar.base = (size_t)t * 8388608; ar.sq = 512; ar.sn = 32768; ar.n0 = n0;
    conv_accum(acc, ar);

    const int lane = threadIdx.x & 31, wid = threadIdx.x >> 5;
    const int wm = wid >> 2, wn = wid & 3;
    const int ocp0 = mt * 128;
    float* dst = (ocp0 < 512) ? g_q : (ocp0 < 1024) ? g_k : g_v;
    const int ocb = ocp0 & 511;
#pragma unroll
    for (int mf = 0; mf < 4; mf++)
#pragma unroll
        for (int nb = 0; nb < 4; nb++) {
            int ocr = ocb + wm * 64 + mf * 16 + (lane >> 2);
            int j0 = wn * 32 + nb * 8 + (lane & 3) * 2;
#pragma unroll
            for (int pr = 0; pr < 2; pr++) {
                int oc = ocr + pr * 8;
#pragma unroll
                for (int e = 0; e < 2; e++) {
                    int j = j0 + e;
                    int n = n0 + (j >> 6), p = j & 63;
                    dst[(size_t)(t * 64 + p) * SLAB + (size_t)n * 512 + oc] =
                        acc[mf][nb][pr * 2 + e];
                }
            }
        }
}

// ---------------- conv out: out = x + conv(virt, Wc) ----------------
__global__ __launch_bounds__(256, 2) void hconv_out_kernel(const float* __restrict__ x,
                                                           float* __restrict__ out) {
    float acc[4][4][4];
#pragma unroll
    for (int a = 0; a < 4; a++)
#pragma unroll
        for (int b = 0; b < 4; b++)
#pragma unroll
            for (int c = 0; c < 4; c++) acc[a][b][c] = 0.f;

    const int mt = blockIdx.x;            // 0..3
    const int y  = blockIdx.y;            // 0..511
    const int t = y >> 7, n0 = (y & 127) * 2;

    ConvArgs ar;
    ar.w = g_wc; ar.ocw = 512; ar.oc0 = mt * 128;
    ar.dh = g_vh; ar.dl = g_vl;
    ar.base = (size_t)t * 8388608; ar.sq = 131072; ar.sn = 512; ar.n0 = n0;
    conv_accum(acc, ar);

    const int lane = threadIdx.x & 31, wid = threadIdx.x >> 5;
    const int wm = wid >> 2, wn = wid & 3;
    const int oc0 = mt * 128;
#pragma unroll
    for (int mf = 0; mf < 4; mf++)
#pragma unroll
        for (int nb = 0; nb < 4; nb++) {
            int ocr = oc0 + wm * 64 + mf * 16 + (lane >> 2);
            int j0 = wn * 32 + nb * 8 + (lane & 3) * 2;
#pragma unroll
            for (int pr = 0; pr < 2; pr++) {
                int oc = ocr + pr * 8;
#pragma unroll
                for (int e = 0; e < 2; e++) {
                    int j = j0 + e;
                    int n = n0 + (j >> 6), p = j & 63;
                    size_t gi = (((size_t)n * 512 + oc) * 4 + t) * 64 + p;
                    out[gi] = x[gi] + acc[mf][nb][pr * 2 + e];
                }
            }
        }
}

// ---------------- attention (SIMT fp32, validated in R2) ----------------
__global__ __launch_bounds__(256) void attn_scores_kernel(const int* __restrict__ roi) {
    __shared__ __align__(16) float sQ[32 * 68];
    __shared__ __align__(16) float sK[32 * 68];
    const int tid = threadIdx.x;
    const int tx = tid & 15, ty = tid >> 4;
    const int loc = blockIdx.y;
    const int it = blockIdx.x >> 2, jt = blockIdx.x & 3;
    const int i0 = it * 64, j0 = jt * 64;
    const size_t qb = (size_t)loc * SLAB + (size_t)i0 * C_;
    const size_t kb = (size_t)loc * SLAB + (size_t)j0 * C_;
    float acc[4][4];
#pragma unroll
    for (int i = 0; i < 4; i++)
#pragma unroll
        for (int j = 0; j < 4; j++) acc[i][j] = 0.f;

    for (int cc = 0; cc < C_; cc += 32) {
#pragma unroll
        for (int u = 0; u < 2; u++) {
            int idx = u * 256 + tid;
            int r = idx >> 3, co = idx & 7;
            float4 vq = *(const float4*)&g_q[qb + (size_t)r * C_ + cc + co * 4];
            float4 vk = *(const float4*)&g_k[kb + (size_t)r * C_ + cc + co * 4];
            sQ[(co * 4 + 0) * 68 + r] = vq.x; sQ[(co * 4 + 1) * 68 + r] = vq.y;
            sQ[(co * 4 + 2) * 68 + r] = vq.z; sQ[(co * 4 + 3) * 68 + r] = vq.w;
            sK[(co * 4 + 0) * 68 + r] = vk.x; sK[(co * 4 + 1) * 68 + r] = vk.y;
            sK[(co * 4 + 2) * 68 + r] = vk.z; sK[(co * 4 + 3) * 68 + r] = vk.w;
        }
        __syncthreads();
#pragma unroll 8
        for (int kk = 0; kk < 32; kk++) {
            float4 a = *(const float4*)&sQ[kk * 68 + (ty << 2)];
            float4 b = *(const float4*)&sK[kk * 68 + (tx << 2)];
            acc[0][0] += a.x * b.x; acc[0][1] += a.x * b.y; acc[0][2] += a.x * b.z; acc[0][3] += a.x * b.w;
            acc[1][0] += a.y * b.x; acc[1][1] += a.y * b.y; acc[1][2] += a.y * b.z; acc[1][3] += a.y * b.w;
            acc[2][0] += a.z * b.x; acc[2][1] += a.z * b.y; acc[2][2] += a.z * b.z; acc[2][3] += a.z * b.w;
            acc[3][0] += a.w * b.x; acc[3][1] += a.w * b.y; acc[3][2] += a.w * b.z; acc[3][3] += a.w * b.w;
        }
        __syncthreads();
    }
    const float scale = 0.044194173824159216f;
    int ri[4], rj[4];
#pragma unroll
    for (int i = 0; i < 4; i++) ri[i] = roi[i0 + (ty << 2) + i];
#pragma unroll
    for (int j = 0; j < 4; j++) rj[j] = roi[j0 + (tx << 2) + j];
#pragma unroll
    for (int i = 0; i < 4; i++) {
        float4 o;
        o.x = (ri[i] == rj[0]) ? acc[i][0] * scale : -1e30f;
        o.y = (ri[i] == rj[1]) ? acc[i][1] * scale : -1e30f;
        o.z = (ri[i] == rj[2]) ? acc[i][2] * scale : -1e30f;
        o.w = (ri[i] == rj[3]) ? acc[i][3] * scale : -1e30f;
        size_t base = (size_t)loc * 65536 + (size_t)(i0 + (ty << 2) + i) * 256 + j0 + (tx << 2);
        *(float4*)&g_att[base] = o;
    }
}

__global__ __launch_bounds__(256) void softmax_kernel() {
    int row = blockIdx.x * 8 + (threadIdx.x >> 5);
    int lane = threadIdx.x & 31;
    float4* base = (float4*)(g_att + (size_t)row * 256);
    float4 v0 = base[lane];
    float4 v1 = base[lane + 32];
    float m = fmaxf(fmaxf(fmaxf(v0.x, v0.y), fmaxf(v0.z, v0.w)),
                    fmaxf(fmaxf(v1.x, v1.y), fmaxf(v1.z, v1.w)));
#pragma unroll
    for (int o = 16; o; o >>= 1) m = fmaxf(m, __shfl_xor_sync(0xffffffffu, m, o));
    v0.x = expf(v0.x - m); v0.y = expf(v0.y - m); v0.z = expf(v0.z - m); v0.w = expf(v0.w - m);
    v1.x = expf(v1.x - m); v1.y = expf(v1.y - m); v1.z = expf(v1.z - m); v1.w = expf(v1.w - m);
    float s = v0.x + v0.y + v0.z + v0.w + v1.x + v1.y + v1.z + v1.w;
#pragma unroll
    for (int o = 16; o; o >>= 1) s += __shfl_xor_sync(0xffffffffu, s, o);
    float inv = 1.f / s;
    v0.x *= inv; v0.y *= inv; v0.z *= inv; v0.w *= inv;
    v1.x *= inv; v1.y *= inv; v1.z *= inv; v1.w *= inv;
    base[lane] = v0;
    base[lane + 32] = v1;
}

__global__ __launch_bounds__(256) void attn_v_kernel() {
    __shared__ __align__(16) float sA[32 * 68];
    __shared__ __align__(16) float sV[32 * 68];
    const int tid = threadIdx.x;
    const int tx = tid & 15, ty = tid >> 4;
    const int loc = blockIdx.y;
    const int it = blockIdx.x >> 3, ct = blockIdx.x & 7;
    const int i0 = it * 64, c0 = ct * 64;
    float acc[4][4];
#pragma unroll
    for (int i = 0; i < 4; i++)
#pragma unroll
        for (int j = 0; j < 4; j++) acc[i][j] = 0.f;

    for (int cc = 0; cc < 256; cc += 32) {
#pragma unroll
        for (int u = 0; u < 2; u++) {
            int idx = u * 256 + tid;
            {
                int r = idx >> 3, co = idx & 7;
                float4 va = *(const float4*)&g_att[(size_t)loc * 65536 +
                                                   (size_t)(i0 + r) * 256 + cc + co * 4];
                sA[(co * 4 + 0) * 68 + r] = va.x; sA[(co * 4 + 1) * 68 + r] = va.y;
                sA[(co * 4 + 2) * 68 + r] = va.z; sA[(co * 4 + 3) * 68 + r] = va.w;
            }
            {
                int jr = idx >> 4, co = idx & 15;
                float4 vv = *(const float4*)&g_v[(size_t)loc * SLAB +
                                                 (size_t)(cc + jr) * C_ + c0 + co * 4];
                *(float4*)&sV[jr * 68 + co * 4] = vv;
            }
        }
        __syncthreads();
#pragma unroll 8
        for (int kk = 0; kk < 32; kk++) {
            float4 a = *(const float4*)&sA[kk * 68 + (ty << 2)];
            float4 b = *(const float4*)&sV[kk * 68 + (tx << 2)];
            acc[0][0] += a.x * b.x; acc[0][1] += a.x * b.y; acc[0][2] += a.x * b.z; acc[0][3] += a.x * b.w;
            acc[1][0] += a.y * b.x; acc[1][1] += a.y * b.y; acc[1][2] += a.y * b.z; acc[1][3] += a.y * b.w;
            acc[2][0] += a.z * b.x; acc[2][1] += a.z * b.y; acc[2][2] += a.z * b.z; acc[2][3] += a.z * b.w;
            acc[3][0] += a.w * b.x; acc[3][1] += a.w * b.y; acc[3][2] += a.w * b.z; acc[3][3] += a.w * b.w;
        }
        __syncthreads();
    }
#pragma unroll
    for (int i = 0; i < 4; i++) {
        size_t base = (size_t)loc * SLAB + (size_t)(i0 + (ty << 2) + i) * C_ + c0 + (tx << 2);
        *(float4*)&g_virt[base] = make_float4(acc[i][0], acc[i][1], acc[i][2], acc[i][3]);
    }
}

// ---------------- GroupNorm ----------------
__global__ __launch_bounds__(256) void gn_stats_kernel() {
    const int n = blockIdx.x, tid = threadIdx.x;
    float s = 0.f, sq = 0.f;
    for (int loc = 0; loc < 256; loc++) {
        size_t base = (size_t)loc * SLAB + (size_t)n * C_;
        float a = g_virt[base + tid];
        float b = g_virt[base + tid + 256];
        s += a + b;
        sq += a * a + b * b;
    }
    __shared__ float rs[256], rq[256];
    rs[tid] = s; rq[tid] = sq;
    __syncthreads();
    for (int o = 128; o > 0; o >>= 1) {
        if (tid < o) { rs[tid] += rs[tid + o]; rq[tid] += rq[tid + o]; }
        __syncthreads();
    }
    if (tid == 0) {
        const float inv = 1.f / 131072.f;
        float mu = rs[0] * inv;
        float var = rq[0] * inv - mu * mu;
        g_stats[n] = make_float2(mu, rsqrtf(var + 1e-5f));
    }
}

// normalize + relu + fp16 hi/lo split for the output conv
__global__ __launch_bounds__(256) void gn_norm_kernel(const float* __restrict__ gamma,
                                                      const float* __restrict__ beta) {
    size_t i = (size_t)blockIdx.x * 256 + threadIdx.x;
    int c = (int)(i & 511);
    int n = (int)((i >> 9) & 255);
    float2 st = g_stats[n];
    float val = fmaxf((g_virt[i] - st.x) * st.y * gamma[c] + beta[c], 0.f);
    __half h = __float2half_rn(val);
    g_vh[i] = h;
    g_vl[i] = __float2half_rn(val - __half2float(h));
}

// ---------------- launch ----------------
extern "C" void kernel_launch(void* const* d_in, const int* in_sizes, int n_in,
                              void* d_out, int out_size) {
    const float* x     = (const float*)d_in[0];
    const int*   roi   = (const int*)d_in[1];
    const float* Wq    = (const float*)d_in[2];
    const float* Wk    = (const float*)d_in[3];
    const float* Wv    = (const float*)d_in[4];
    const float* Wc    = (const float*)d_in[5];
    const float* gamma = (const float*)d_in[6];
    const float* beta  = (const float*)d_in[7];
    float* out = (float*)d_out;

    cudaFuncSetAttribute(hconv_qkv_kernel, cudaFuncAttributeMaxDynamicSharedMemorySize, 98304);
    cudaFuncSetAttribute(hconv_out_kernel, cudaFuncAttributeMaxDynamicSharedMemorySize, 98304);

    pack_x_kernel<<<dim3(8, 1024), 256>>>(x);
    pack_wqkv_kernel<<<27648, 256>>>(Wq, Wk, Wv);
    pack_wc_kernel<<<9216, 256>>>(Wc);

    hconv_qkv_kernel<<<dim3(12, 512), 256, 98304>>>();

    attn_scores_kernel<<<dim3(16, 256), 256>>>(roi);
    softmax_kernel<<<8192, 256>>>();
    attn_v_kernel<<<dim3(32, 256), 256>>>();

    gn_stats_kernel<<<256, 256>>>();
    gn_norm_kernel<<<131072, 256>>>(gamma, beta);

    hconv_out_kernel<<<dim3(4, 512), 256, 98304>>>(x, out);
}

// round 5
// speedup vs baseline: 10.1274x; 2.3946x over previous
#include <cuda_runtime.h>
#include <cuda_fp16.h>
#include <math.h>
#include <stdint.h>

// ---------------- problem constants ----------------
#define C_    512
#define SLAB  131072            // 256*512

// ---------------- device scratch ----------------
__device__ __align__(256) float g_virt[33554432];   // [loc][n][c] fp32 (pre-GN)
__device__ __align__(256) float g_att[16777216];    // [loc][i][j] fp32 scores
__device__ float2 g_stats[256];

__device__ __align__(256) __half g_xh[33554432];    // x fp16 [t][n][pix][ic]
__device__ __align__(256) __half g_vh[33554432];    // virt post-GN fp16 [loc][n][c]
__device__ __align__(256) __half g_qh[33554432];    // q fp16 [loc][n][c]
__device__ __align__(256) __half g_kh[33554432];    // k fp16 [loc][n][c]
__device__ __align__(256) __half g_vT[33554432];    // v fp16 [loc][c][n]
__device__ __align__(256) __half g_att16[16777216]; // att fp16 [loc][i][j]
__device__ __align__(256) __half g_wq[7077888];     // [tap][ocp(1536)][ic]
__device__ __align__(256) __half g_wc[2359296];     // [tap][oc][ic]

// ---------------- asm helpers ----------------
__device__ __forceinline__ uint32_t smem_u32_of(const void* p) {
    uint32_t a;
    asm("{ .reg .u64 t; cvta.to.shared.u64 t, %1; cvt.u32.u64 %0, t; }" : "=r"(a) : "l"(p));
    return a;
}
#define CPA(dst, src, sz) \
    asm volatile("cp.async.cg.shared.global [%0], [%1], 16, %2;" \
        :: "r"(dst), "l"(src), "r"(sz) : "memory")
#define CPA_COMMIT() asm volatile("cp.async.commit_group;" ::: "memory")
#define CPA_WAIT2() asm volatile("cp.async.wait_group 2;" ::: "memory")
#define CPA_WAIT1() asm volatile("cp.async.wait_group 1;" ::: "memory")
#define CPA_WAIT0() asm volatile("cp.async.wait_group 0;" ::: "memory")

__device__ __forceinline__ void ldsm4(uint32_t r[4], uint32_t addr) {
    asm volatile("ldmatrix.sync.aligned.m8n8.x4.shared.b16 {%0,%1,%2,%3}, [%4];"
        : "=r"(r[0]), "=r"(r[1]), "=r"(r[2]), "=r"(r[3]) : "r"(addr));
}
__device__ __forceinline__ void mma16816(float c[4], const uint32_t a[4],
                                         uint32_t b0, uint32_t b1) {
    asm volatile(
        "mma.sync.aligned.m16n8k16.row.col.f32.f16.f16.f32 "
        "{%0,%1,%2,%3}, {%4,%5,%6,%7}, {%8,%9}, {%0,%1,%2,%3};"
        : "+f"(c[0]), "+f"(c[1]), "+f"(c[2]), "+f"(c[3])
        : "r"(a[0]), "r"(a[1]), "r"(a[2]), "r"(a[3]), "r"(b0), "r"(b1));
}

// ---------------- shared MMA stage (128x128 tile, K=64), plain B ----------------
__device__ __forceinline__ void mma_stage(float acc[4][4][4], uint32_t aB, uint32_t bB,
                                          int lane, int wm, int wn) {
#pragma unroll
    for (int ks = 0; ks < 4; ks++) {
        uint32_t Af[4][4];
#pragma unroll
        for (int mf = 0; mf < 4; mf++) {
            int r = wm * 64 + mf * 16 + (lane & 7) + ((lane >> 3) & 1) * 8;
            int kc = ks * 2 + (lane >> 4);
            ldsm4(Af[mf], aB + r * 128 + 16 * (kc ^ (r & 7)));
        }
#pragma unroll
        for (int nb2 = 0; nb2 < 2; nb2++) {
            uint32_t Bf[4];
            int r = wn * 32 + nb2 * 16 + (lane & 7) + ((lane >> 4) << 3);
            int kc = ks * 2 + ((lane >> 3) & 1);
            ldsm4(Bf, bB + r * 128 + 16 * (kc ^ (r & 7)));
#pragma unroll
            for (int mf = 0; mf < 4; mf++) {
                mma16816(acc[mf][nb2 * 2 + 0], Af[mf], Bf[0], Bf[1]);
                mma16816(acc[mf][nb2 * 2 + 1], Af[mf], Bf[2], Bf[3]);
            }
        }
    }
}

// conv variant: B rows are a tap-shifted view of the X tile (row 128 = zeros)
__device__ __forceinline__ void mma_stage_conv(float acc[4][4][4], uint32_t aB, uint32_t xB,
                                               int lane, int wm, int wn, int dh, int dw) {
#pragma unroll
    for (int ks = 0; ks < 4; ks++) {
        uint32_t Af[4][4];
#pragma unroll
        for (int mf = 0; mf < 4; mf++) {
            int r = wm * 64 + mf * 16 + (lane & 7) + ((lane >> 3) & 1) * 8;
            int kc = ks * 2 + (lane >> 4);
            ldsm4(Af[mf], aB + r * 128 + 16 * (kc ^ (r & 7)));
        }
#pragma unroll
        for (int nb2 = 0; nb2 < 2; nb2++) {
            uint32_t Bf[4];
            int rj = wn * 32 + nb2 * 16 + (lane & 7) + ((lane >> 4) << 3);
            int p = rj & 63, n = rj >> 6;
            int hh = (p >> 3) + dh, ww = (p & 7) + dw;
            bool ok = ((unsigned)hh < 8u) && ((unsigned)ww < 8u);
            int row = ok ? ((n << 6) + (hh << 3) + ww) : 128;
            int kc = ks * 2 + ((lane >> 3) & 1);
            ldsm4(Bf, xB + row * 128 + 16 * (kc ^ (row & 7)));
#pragma unroll
            for (int mf = 0; mf < 4; mf++) {
                mma16816(acc[mf][nb2 * 2 + 0], Af[mf], Bf[0], Bf[1]);
                mma16816(acc[mf][nb2 * 2 + 1], Af[mf], Bf[2], Bf[3]);
            }
        }
    }
}

// ---------------- prepack ----------------
__global__ __launch_bounds__(256) void pack_x_kernel(const float* __restrict__ x) {
    __shared__ float sT[64 * 65];
    int icb = blockIdx.x, nt = blockIdx.y;
    int n = nt >> 2, t = nt & 3;
    int ic0 = icb * 64, tid = threadIdx.x;
#pragma unroll 4
    for (int rep = 0; rep < 16; rep++) {
        int e = rep * 256 + tid;
        int i = e >> 6, p = e & 63;
        sT[i * 65 + p] = x[(((size_t)n * C_ + ic0 + i) * 4 + t) * 64 + p];
    }
    __syncthreads();
#pragma unroll 4
    for (int rep = 0; rep < 16; rep++) {
        int e = rep * 256 + tid;
        int p = e >> 6, i = e & 63;
        g_xh[(size_t)t * 8388608 + (size_t)n * 32768 + (size_t)p * 512 + ic0 + i] =
            __float2half_rn(sT[i * 65 + p]);
    }
}

__global__ __launch_bounds__(256) void pack_wqkv_kernel(const float* __restrict__ wq,
                                                        const float* __restrict__ wk,
                                                        const float* __restrict__ wv) {
    int idx = blockIdx.x * 256 + threadIdx.x;
    if (idx >= 7077888) return;
    int ic = idx & 511, ocp = (idx >> 9) % 1536, tap = idx / (1536 * 512);
    const float* src = (ocp < 512) ? wq : (ocp < 1024) ? wk : wv;
    int oc = ocp & 511;
    g_wq[idx] = __float2half_rn(src[((size_t)oc * 512 + ic) * 9 + tap]);
}

__global__ __launch_bounds__(256) void pack_wc_kernel(const float* __restrict__ wc) {
    int idx = blockIdx.x * 256 + threadIdx.x;
    if (idx >= 2359296) return;
    int ic = idx & 511, oc = (idx >> 9) & 511, tap = idx >> 18;
    g_wc[idx] = __float2half_rn(wc[((size_t)oc * 512 + ic) * 9 + tap]);
}

// ---------------- conv core: A-stream (72 tiles) + X-stream (8 tiles) ----------------
#define CSM_A   0
#define CSM_X   49152
#define CSM_TOT (49152 + 2 * 16640)     // 82432

struct ConvArgs {
    const __half* w; int ocw; int oc0;
    const __half* d; size_t base; int sq; int sn; int n0;
};

__device__ __forceinline__ void conv_core(float acc[4][4][4], const ConvArgs& A_) {
    extern __shared__ char smem[];
    const uint32_t smem_b = smem_u32_of(smem);
    const int tid = threadIdx.x;
    const int lane = tid & 31, wid = tid >> 5;
    const int wm = wid >> 2, wn = wid & 3;

    if (tid < 64) {   // zero halo rows (row 128 of both X buffers)
        int b = tid >> 5, c = tid & 31;
        *(float*)(smem + CSM_X + b * 16640 + 128 * 128 + c * 4) = 0.f;
    }

    auto loadA = [&](int s) {
        int tap = s % 9;
        uint32_t ab = smem_b + CSM_A + (s % 3) * 16384;
#pragma unroll
        for (int kk = 0; kk < 4; kk++) {
            int q = tid + kk * 256;
            int r = q >> 3, c = q & 7;
            const __half* src = A_.w +
                ((size_t)(tap * A_.ocw + A_.oc0 + r)) * 512 + (s / 9) * 64 + c * 8;
            CPA(ab + r * 128 + 16 * (c ^ (r & 7)), src, 16);
        }
    };
    auto loadX = [&](int icb) {
        uint32_t xb = smem_b + CSM_X + (icb & 1) * 16640;
#pragma unroll
        for (int kk = 0; kk < 4; kk++) {
            int q = tid + kk * 256;
            int r = q >> 3, c = q & 7;
            int n = A_.n0 + (r >> 6), p = r & 63;
            const __half* src = A_.d + A_.base + (size_t)p * A_.sq +
                (size_t)n * A_.sn + icb * 64 + c * 8;
            CPA(xb + r * 128 + 16 * (c ^ (r & 7)), src, 16);
        }
    };

    loadA(0); loadX(0); CPA_COMMIT();
    loadA(1); loadX(1); CPA_COMMIT();
    loadA(2); CPA_COMMIT();

    for (int s = 0; s < 72; s++) {
        if (s < 69) CPA_WAIT2(); else CPA_WAIT0();
        __syncthreads();
        int tap = s % 9;
        mma_stage_conv(acc, smem_b + CSM_A + (s % 3) * 16384,
                       smem_b + CSM_X + ((s / 9) & 1) * 16640,
                       lane, wm, wn, tap / 3 - 1, tap % 3 - 1);
        __syncthreads();
        if (s < 69) {
            loadA(s + 3);
            if (s % 9 == 6 && (s / 9 + 1) < 8) loadX(s / 9 + 1);
            CPA_COMMIT();
        }
    }
}

// ---------------- conv qkv: epilogue -> q,k fp16 [loc][n][c]; v fp16 [loc][c][n] ----
__global__ __launch_bounds__(256, 2) void hconv_qkv_kernel() {
    float acc[4][4][4];
#pragma unroll
    for (int a = 0; a < 4; a++)
#pragma unroll
        for (int b = 0; b < 4; b++)
#pragma unroll
            for (int c = 0; c < 4; c++) acc[a][b][c] = 0.f;

    const int mt = blockIdx.x, y = blockIdx.y;
    const int t = y >> 7, n0 = (y & 127) * 2;

    ConvArgs ar;
    ar.w = g_wq; ar.ocw = 1536; ar.oc0 = mt * 128;
    ar.d = g_xh; ar.base = (size_t)t * 8388608; ar.sq = 512; ar.sn = 32768; ar.n0 = n0;
    conv_core(acc, ar);

    const int lane = threadIdx.x & 31, wid = threadIdx.x >> 5;
    const int wm = wid >> 2, wn = wid & 3;
    const int kind = mt >> 2;             // 0=q 1=k 2=v
    const int ocb = (mt * 128) & 511;
    __half* dsth = (kind == 0) ? g_qh : g_kh;
#pragma unroll
    for (int mf = 0; mf < 4; mf++)
#pragma unroll
        for (int nb = 0; nb < 4; nb++)
#pragma unroll
            for (int pr = 0; pr < 2; pr++) {
                int oc = ocb + wm * 64 + mf * 16 + (lane >> 2) + pr * 8;
#pragma unroll
                for (int e = 0; e < 2; e++) {
                    int j = wn * 32 + nb * 8 + (lane & 3) * 2 + e;
                    int n = n0 + (j >> 6), p = j & 63;
                    __half hv = __float2half_rn(acc[mf][nb][pr * 2 + e]);
                    size_t loc = (size_t)(t * 64 + p);
                    if (kind == 2)
                        g_vT[loc * 131072 + (size_t)oc * 256 + n] = hv;
                    else
                        dsth[loc * 131072 + (size_t)n * 512 + oc] = hv;
                }
            }
}

// ---------------- conv out: out = x + conv(virt_h, Wc) ----------------
__global__ __launch_bounds__(256, 2) void hconv_out_kernel(const float* __restrict__ x,
                                                           float* __restrict__ out) {
    float acc[4][4][4];
#pragma unroll
    for (int a = 0; a < 4; a++)
#pragma unroll
        for (int b = 0; b < 4; b++)
#pragma unroll
            for (int c = 0; c < 4; c++) acc[a][b][c] = 0.f;

    const int mt = blockIdx.x, y = blockIdx.y;
    const int t = y >> 7, n0 = (y & 127) * 2;

    ConvArgs ar;
    ar.w = g_wc; ar.ocw = 512; ar.oc0 = mt * 128;
    ar.d = g_vh; ar.base = (size_t)t * 8388608; ar.sq = 131072; ar.sn = 512; ar.n0 = n0;
    conv_core(acc, ar);

    const int lane = threadIdx.x & 31, wid = threadIdx.x >> 5;
    const int wm = wid >> 2, wn = wid & 3;
    const int oc0 = mt * 128;
#pragma unroll
    for (int mf = 0; mf < 4; mf++)
#pragma unroll
        for (int nb = 0; nb < 4; nb++)
#pragma unroll
            for (int pr = 0; pr < 2; pr++) {
                int oc = oc0 + wm * 64 + mf * 16 + (lane >> 2) + pr * 8;
#pragma unroll
                for (int e = 0; e < 2; e++) {
                    int j = wn * 32 + nb * 8 + (lane & 3) * 2 + e;
                    int n = n0 + (j >> 6), p = j & 63;
                    size_t gi = (((size_t)n * 512 + oc) * 4 + t) * 64 + p;
                    out[gi] = x[gi] + acc[mf][nb][pr * 2 + e];
                }
            }
}

// ---------------- attention scores (HMMA): S = scale*q.k^T masked ----------------
__global__ __launch_bounds__(256, 2) void attn_scores_tc(const int* __restrict__ roi) {
    float acc[4][4][4];
#pragma unroll
    for (int a = 0; a < 4; a++)
#pragma unroll
        for (int b = 0; b < 4; b++)
#pragma unroll
            for (int c = 0; c < 4; c++) acc[a][b][c] = 0.f;

    extern __shared__ char smem[];
    const uint32_t smem_b = smem_u32_of(smem);
    const int tid = threadIdx.x, lane = tid & 31, wid = tid >> 5;
    const int wm = wid >> 2, wn = wid & 3;
    const int loc = blockIdx.y;
    const int i0 = (blockIdx.x >> 1) * 128, j0 = (blockIdx.x & 1) * 128;
    const __half* qb = g_qh + (size_t)loc * 131072;
    const __half* kb = g_kh + (size_t)loc * 131072;

    auto load = [&](int s) {
        uint32_t ab = smem_b + (s % 3) * 32768;
#pragma unroll
        for (int kk = 0; kk < 8; kk++) {
            int task = tid + kk * 256;
            int reg = task >> 10, q2 = task & 1023;
            int r = q2 >> 3, c = q2 & 7;
            const __half* src = (reg == 0)
                ? qb + (size_t)(i0 + r) * 512 + s * 64 + c * 8
                : kb + (size_t)(j0 + r) * 512 + s * 64 + c * 8;
            CPA(ab + reg * 16384 + r * 128 + 16 * (c ^ (r & 7)), src, 16);
        }
        CPA_COMMIT();
    };
    load(0); load(1); load(2);
    for (int s = 0; s < 8; s++) {
        if (s < 6) CPA_WAIT2(); else if (s == 6) CPA_WAIT1(); else CPA_WAIT0();
        __syncthreads();
        uint32_t ab = smem_b + (s % 3) * 32768;
        mma_stage(acc, ab, ab + 16384, lane, wm, wn);
        __syncthreads();
        if (s + 3 < 8) load(s + 3);
    }
    const float scale = 0.044194173824159216f;
    float* outp = g_att + (size_t)loc * 65536;
#pragma unroll
    for (int mf = 0; mf < 4; mf++)
#pragma unroll
        for (int pr = 0; pr < 2; pr++) {
            int i = i0 + wm * 64 + mf * 16 + (lane >> 2) + pr * 8;
            int ri = __ldg(&roi[i]);
#pragma unroll
            for (int nb = 0; nb < 4; nb++) {
                int j = j0 + wn * 32 + nb * 8 + (lane & 3) * 2;
                float2 v;
                v.x = (ri == __ldg(&roi[j]))     ? acc[mf][nb][pr * 2 + 0] * scale : -1e30f;
                v.y = (ri == __ldg(&roi[j + 1])) ? acc[mf][nb][pr * 2 + 1] * scale : -1e30f;
                *(float2*)&outp[(size_t)i * 256 + j] = v;
            }
        }
}

// ---------------- softmax (fp32 in, fp16 out) ----------------
__global__ __launch_bounds__(256) void softmax_kernel() {
    int row = blockIdx.x * 8 + (threadIdx.x >> 5);
    int lane = threadIdx.x & 31;
    const float4* base = (const float4*)(g_att + (size_t)row * 256);
    float4 v0 = base[lane];
    float4 v1 = base[lane + 32];
    float m = fmaxf(fmaxf(fmaxf(v0.x, v0.y), fmaxf(v0.z, v0.w)),
                    fmaxf(fmaxf(v1.x, v1.y), fmaxf(v1.z, v1.w)));
#pragma unroll
    for (int o = 16; o; o >>= 1) m = fmaxf(m, __shfl_xor_sync(0xffffffffu, m, o));
    v0.x = expf(v0.x - m); v0.y = expf(v0.y - m); v0.z = expf(v0.z - m); v0.w = expf(v0.w - m);
    v1.x = expf(v1.x - m); v1.y = expf(v1.y - m); v1.z = expf(v1.z - m); v1.w = expf(v1.w - m);
    float s = v0.x + v0.y + v0.z + v0.w + v1.x + v1.y + v1.z + v1.w;
#pragma unroll
    for (int o = 16; o; o >>= 1) s += __shfl_xor_sync(0xffffffffu, s, o);
    float inv = 1.f / s;
    __half2* ob = (__half2*)(g_att16 + (size_t)row * 256);
    ob[lane * 2 + 0] = __floats2half2_rn(v0.x * inv, v0.y * inv);
    ob[lane * 2 + 1] = __floats2half2_rn(v0.z * inv, v0.w * inv);
    ob[(lane + 32) * 2 + 0] = __floats2half2_rn(v1.x * inv, v1.y * inv);
    ob[(lane + 32) * 2 + 1] = __floats2half2_rn(v1.z * inv, v1.w * inv);
}

// ---------------- virt = att @ v (HMMA) -> g_virt fp32 [loc][n][c] ----------------
__global__ __launch_bounds__(256, 2) void attn_v_tc() {
    float acc[4][4][4];
#pragma unroll
    for (int a = 0; a < 4; a++)
#pragma unroll
        for (int b = 0; b < 4; b++)
#pragma unroll
            for (int c = 0; c < 4; c++) acc[a][b][c] = 0.f;

    extern __shared__ char smem[];
    const uint32_t smem_b = smem_u32_of(smem);
    const int tid = threadIdx.x, lane = tid & 31, wid = tid >> 5;
    const int wm = wid >> 2, wn = wid & 3;
    const int loc = blockIdx.y;
    const int i0 = (blockIdx.x >> 2) * 128, c0 = (blockIdx.x & 3) * 128;
    const __half* ab_g = g_att16 + (size_t)loc * 65536;
    const __half* bb_g = g_vT + (size_t)loc * 131072;

    auto load = [&](int s) {
        uint32_t ab = smem_b + (s % 3) * 32768;
#pragma unroll
        for (int kk = 0; kk < 8; kk++) {
            int task = tid + kk * 256;
            int reg = task >> 10, q2 = task & 1023;
            int r = q2 >> 3, c = q2 & 7;
            const __half* src = (reg == 0)
                ? ab_g + (size_t)(i0 + r) * 256 + s * 64 + c * 8
                : bb_g + (size_t)(c0 + r) * 256 + s * 64 + c * 8;
            CPA(ab + reg * 16384 + r * 128 + 16 * (c ^ (r & 7)), src, 16);
        }
        CPA_COMMIT();
    };
    load(0); load(1); load(2);
    for (int s = 0; s < 4; s++) {
        if (s < 2) CPA_WAIT2(); else if (s == 2) CPA_WAIT1(); else CPA_WAIT0();
        __syncthreads();
        uint32_t ab = smem_b + (s % 3) * 32768;
        mma_stage(acc, ab, ab + 16384, lane, wm, wn);
        __syncthreads();
        if (s + 3 < 4) load(s + 3);
    }
    float* outp = g_virt + (size_t)loc * 131072;
#pragma unroll
    for (int mf = 0; mf < 4; mf++)
#pragma unroll
        for (int pr = 0; pr < 2; pr++) {
            int i = i0 + wm * 64 + mf * 16 + (lane >> 2) + pr * 8;
#pragma unroll
            for (int nb = 0; nb < 4; nb++) {
                int cc = c0 + wn * 32 + nb * 8 + (lane & 3) * 2;
                float2 v = make_float2(acc[mf][nb][pr * 2 + 0], acc[mf][nb][pr * 2 + 1]);
                *(float2*)&outp[(size_t)i * 512 + cc] = v;
            }
        }
}

// ---------------- GroupNorm ----------------
__global__ __launch_bounds__(256) void gn_stats_kernel() {
    const int n = blockIdx.x, tid = threadIdx.x;
    float s = 0.f, sq = 0.f;
    for (int loc = 0; loc < 256; loc++) {
        size_t base = (size_t)loc * SLAB + (size_t)n * C_;
        float a = g_virt[base + tid];
        float b = g_virt[base + tid + 256];
        s += a + b;
        sq += a * a + b * b;
    }
    __shared__ float rs[256], rq[256];
    rs[tid] = s; rq[tid] = sq;
    __syncthreads();
    for (int o = 128; o > 0; o >>= 1) {
        if (tid < o) { rs[tid] += rs[tid + o]; rq[tid] += rq[tid + o]; }
        __syncthreads();
    }
    if (tid == 0) {
        const float inv = 1.f / 131072.f;
        float mu = rs[0] * inv;
        float var = rq[0] * inv - mu * mu;
        g_stats[n] = make_float2(mu, rsqrtf(var + 1e-5f));
    }
}

__global__ __launch_bounds__(256) void gn_norm_kernel(const float* __restrict__ gamma,
                                                      const float* __restrict__ beta) {
    size_t i = (size_t)blockIdx.x * 256 + threadIdx.x;
    int c = (int)(i & 511);
    int n = (int)((i >> 9) & 255);
    float2 st = g_stats[n];
    float val = fmaxf((g_virt[i] - st.x) * st.y * gamma[c] + beta[c], 0.f);
    g_vh[i] = __float2half_rn(val);
}

// ---------------- launch ----------------
extern "C" void kernel_launch(void* const* d_in, const int* in_sizes, int n_in,
                              void* d_out, int out_size) {
    const float* x     = (const float*)d_in[0];
    const int*   roi   = (const int*)d_in[1];
    const float* Wq    = (const float*)d_in[2];
    const float* Wk    = (const float*)d_in[3];
    const float* Wv    = (const float*)d_in[4];
    const float* Wc    = (const float*)d_in[5];
    const float* gamma = (const float*)d_in[6];
    const float* beta  = (const float*)d_in[7];
    float* out = (float*)d_out;

    cudaFuncSetAttribute(hconv_qkv_kernel, cudaFuncAttributeMaxDynamicSharedMemorySize, CSM_TOT);
    cudaFuncSetAttribute(hconv_out_kernel, cudaFuncAttributeMaxDynamicSharedMemorySize, CSM_TOT);
    cudaFuncSetAttribute(attn_scores_tc, cudaFuncAttributeMaxDynamicSharedMemorySize, 98304);
    cudaFuncSetAttribute(attn_v_tc, cudaFuncAttributeMaxDynamicSharedMemorySize, 98304);

    pack_x_kernel<<<dim3(8, 1024), 256>>>(x);
    pack_wqkv_kernel<<<27648, 256>>>(Wq, Wk, Wv);
    pack_wc_kernel<<<9216, 256>>>(Wc);

    hconv_qkv_kernel<<<dim3(12, 512), 256, CSM_TOT>>>();

    attn_scores_tc<<<dim3(4, 256), 256, 98304>>>(roi);
    softmax_kernel<<<8192, 256>>>();
    attn_v_tc<<<dim3(8, 256), 256, 98304>>>();

    gn_stats_kernel<<<256, 256>>>();
    gn_norm_kernel<<<131072, 256>>>(gamma, beta);

    hconv_out_kernel<<<dim3(4, 512), 256, CSM_TOT>>>(x, out);
}